// round 9
// baseline (speedup 1.0000x reference)
#include <cuda_runtime.h>
#include <cstdint>

// ---------------------------------------------------------------------------
// SDPQuantizer, fused persistent kernel, occupancy-tuned.
// x: (8, 4096, 2048) fp32 = 67,108,864 elements = 16384 tiles of 1024 float4.
//
// 888 CTAs = 148 SMs x 6 (co-residency forced by __launch_bounds__(256,6),
// <=42 regs), each owns a contiguous span of tiles.
//   Phase 1: reduce own span (L2-allocating __ldcg), REDUX + atomic min/max.
//   Grid barrier (sense-reversing, replay-safe: sense goes 0->1->0/launch).
//   Phase 2: quantize own span in REVERSE tile order -> first reads hit the
//     L2 lines this CTA touched last in phase 1 (R8 measured ~100MB reuse).
// R8 post-mortem: reuse worked but 4 CTA/SM / 64 regs shape only sustained
// 4.7 TB/s. This round keeps the reuse and restores the R3-proven 6-CTA/SM
// 40-reg shape that sustains ~6 TB/s.
// ---------------------------------------------------------------------------

#define SDP_NCTAS 888
#define SDP_TPB   256

__device__ unsigned int g_min_enc = 0x80000000u;   // enc(0.0f)
__device__ unsigned int g_max_enc = 0x80000000u;
__device__ unsigned int g_bar_count = 0;
__device__ volatile unsigned int g_bar_sense = 0;

__device__ __forceinline__ unsigned int enc_f(float f) {
    unsigned int u = __float_as_uint(f);
    return (u & 0x80000000u) ? ~u : (u | 0x80000000u);
}
__device__ __forceinline__ float dec_f(unsigned int u) {
    return (u & 0x80000000u) ? __uint_as_float(u & 0x7FFFFFFFu)
                             : __uint_as_float(~u);
}
__device__ __forceinline__ float v4min(float4 v) {
    return fminf(fminf(v.x, v.y), fminf(v.z, v.w));
}
__device__ __forceinline__ float v4max(float4 v) {
    return fmaxf(fmaxf(v.x, v.y), fmaxf(v.z, v.w));
}

// Sense-reversing grid barrier; all SDP_NCTAS CTAs co-resident by
// construction. Last arriver resets count BEFORE flipping sense, so each
// barrier (and each graph replay) starts from count==0.
__device__ __forceinline__ void grid_barrier(unsigned int sense_val) {
    __syncthreads();
    if (threadIdx.x == 0) {
        __threadfence();
        unsigned int old = atomicAdd(&g_bar_count, 1);
        if (old == SDP_NCTAS - 1) {
            g_bar_count = 0;          // spinners only read g_bar_sense
            __threadfence();
            g_bar_sense = sense_val;  // release
        } else {
            while (g_bar_sense != sense_val) __nanosleep(64);
        }
        __threadfence();
    }
    __syncthreads();
}

// compare-exchange: u becomes max, v becomes min
#define SDP_CE(u, v) { float _hi = fmaxf(u, v), _lo = fminf(u, v); u = _hi; v = _lo; }

__device__ __forceinline__ void sdp_process_group(
    float4 va, float4 vb, float scale, float inv_scale,
    float4& oa, float4& ob)
{
    float xv[8]  = {va.x, va.y, va.z, va.w, vb.x, vb.y, vb.z, vb.w};
    float q[8];
    float mag[8];

    #pragma unroll
    for (int i = 0; i < 8; i++) {
        // Reciprocal-multiply fast path; can only flip round-half-to-even on
        // a near-.5 tie: detect and redo with exact IEEE division (rare).
        float y = xv[i] * inv_scale;
        float r = rintf(y);
        if (fabsf(fabsf(y - r) - 0.5f) < 1e-3f) {
            r = rintf(__fdiv_rn(xv[i], scale));
        }
        r = fminf(fmaxf(r, -128.0f), 127.0f);
        q[i]   = r;
        mag[i] = fabsf(r);   // integer-valued, 0..128
    }

    // 4th-largest of 8 via two sorted-4 runs + merge rank selection.
    float a0 = mag[0], a1 = mag[1], a2 = mag[2], a3 = mag[3];
    float b0 = mag[4], b1 = mag[5], b2 = mag[6], b3 = mag[7];
    SDP_CE(a0, a1); SDP_CE(a2, a3); SDP_CE(a0, a2); SDP_CE(a1, a3); SDP_CE(a1, a2);
    SDP_CE(b0, b1); SDP_CE(b2, b3); SDP_CE(b0, b2); SDP_CE(b1, b3); SDP_CE(b1, b2);
    float thr = fmaxf(fmaxf(a3, b3),
                      fmaxf(fminf(a0, b2), fmaxf(fminf(a1, b1), fminf(a2, b0))));

    #pragma unroll
    for (int i = 0; i < 8; i++) {
        const float tr16 = floorf(mag[i] * 0.0625f) * 16.0f;
        const float val  = (mag[i] >= thr) ? mag[i] : tr16;
        const float x_sdp = scale * copysignf(val, q[i]);
        xv[i] = xv[i] + (x_sdp - xv[i]);   // replicate reference rounding
    }

    oa = make_float4(xv[0], xv[1], xv[2], xv[3]);
    ob = make_float4(xv[4], xv[5], xv[6], xv[7]);
}

__global__ void __launch_bounds__(SDP_TPB, 6)
sdp_fused_kernel(const float4* __restrict__ x, float4* __restrict__ out,
                 int ntiles) {
    const int cta = blockIdx.x;
    const int t   = threadIdx.x;
    // Contiguous tile span per CTA (tile = 1024 float4 = 16KB).
    const int tile_lo = (int)(((long long)cta       * ntiles) / SDP_NCTAS);
    const int tile_hi = (int)(((long long)(cta + 1) * ntiles) / SDP_NCTAS);

    // ---- Phase 1: min/max over own span (L2-allocating loads) ----
    float lmin = 0.0f, lmax = 0.0f;
    for (int tile = tile_lo; tile < tile_hi; ++tile) {
        const size_t base = (size_t)tile * 1024 + (size_t)t * 4;
        float4 v0 = __ldcg(&x[base + 0]);
        float4 v1 = __ldcg(&x[base + 1]);
        float4 v2 = __ldcg(&x[base + 2]);
        float4 v3 = __ldcg(&x[base + 3]);
        lmin = fminf(lmin, fminf(fminf(v4min(v0), v4min(v1)),
                                 fminf(v4min(v2), v4min(v3))));
        lmax = fmaxf(lmax, fmaxf(fmaxf(v4max(v0), v4max(v1)),
                                 fmaxf(v4max(v2), v4max(v3))));
    }

    unsigned int emin = __reduce_min_sync(0xFFFFFFFFu, enc_f(lmin));
    unsigned int emax = __reduce_max_sync(0xFFFFFFFFu, enc_f(lmax));
    __shared__ unsigned int smin[8], smax[8];
    const int lane = t & 31;
    const int warp = t >> 5;
    if (lane == 0) { smin[warp] = emin; smax[warp] = emax; }
    __syncthreads();
    if (t < 8) {
        emin = __reduce_min_sync(0xFFu, smin[t]);
        emax = __reduce_max_sync(0xFFu, smax[t]);
        if (t == 0) {
            atomicMin(&g_min_enc, emin);
            atomicMax(&g_max_enc, emax);
        }
    }

    // ---- Grid barrier (sense -> 1) ----
    grid_barrier(1u);

    // ---- Phase 2: quantize own span in reverse tile order ----
    const float r_min = dec_f(*(volatile unsigned int*)&g_min_enc);
    const float r_max = dec_f(*(volatile unsigned int*)&g_max_enc);
    const float scale = fmaxf(__fdiv_rn(r_max - r_min, 255.0f), 1e-8f);
    const float inv_scale = __frcp_rn(scale);

    for (int tile = tile_hi - 1; tile >= tile_lo; --tile) {
        const size_t base = (size_t)tile * 1024 + (size_t)t * 4;
        float4 v0 = __ldcs(&x[base + 0]);
        float4 v1 = __ldcs(&x[base + 1]);
        float4 v2 = __ldcs(&x[base + 2]);
        float4 v3 = __ldcs(&x[base + 3]);

        float4 o0, o1, o2, o3;
        sdp_process_group(v0, v1, scale, inv_scale, o0, o1);
        sdp_process_group(v2, v3, scale, inv_scale, o2, o3);

        __stcs(&out[base + 0], o0);
        __stcs(&out[base + 1], o1);
        __stcs(&out[base + 2], o2);
        __stcs(&out[base + 3], o3);
    }

    // ---- Grid barrier (sense -> 0): restores replay-start state ----
    grid_barrier(0u);
}

extern "C" void kernel_launch(void* const* d_in, const int* in_sizes, int n_in,
                              void* d_out, int out_size) {
    const float* x = (const float*)d_in[0];
    float* out = (float*)d_out;
    const int n = in_sizes[0];          // 67,108,864
    const int n4 = n >> 2;              // 16,777,216 float4
    const int ntiles = n4 >> 10;        // 16384 tiles of 1024 float4

    sdp_fused_kernel<<<SDP_NCTAS, SDP_TPB>>>((const float4*)x, (float4*)out,
                                             ntiles);
}

// round 10
// speedup vs baseline: 1.0925x; 1.0925x over previous
#include <cuda_runtime.h>
#include <cstdint>

// ---------------------------------------------------------------------------
// SDPQuantizer: global min/max -> int8 quantize -> split high/low nibble ->
// per-8-group top-4 mask on low nibble -> dequantize.
// x: (8, 4096, 2048) fp32, 67,108,864 elements (256 MB). Output fp32.
//
// R3-proven two-kernel structure (minmax 49.3us, quant 85.9us) + PDL:
// the quant kernel is launched with programmatic stream serialization, does
// its scale-independent loads BEFORE cudaGridDependencySynchronize(), so its
// first waves overlap the minmax drain and prefetch input early.
// ---------------------------------------------------------------------------

__device__ unsigned int g_min_enc = 0x80000000u;  // enc(0.0f)
__device__ unsigned int g_max_enc = 0x80000000u;

__device__ __forceinline__ unsigned int enc_f(float f) {
    unsigned int u = __float_as_uint(f);
    return (u & 0x80000000u) ? ~u : (u | 0x80000000u);
}
__device__ __forceinline__ float dec_f(unsigned int u) {
    return (u & 0x80000000u) ? __uint_as_float(u & 0x7FFFFFFFu)
                             : __uint_as_float(~u);
}
__device__ __forceinline__ float v4min(float4 v) {
    return fminf(fminf(v.x, v.y), fminf(v.z, v.w));
}
__device__ __forceinline__ float v4max(float4 v) {
    return fmaxf(fmaxf(v.x, v.y), fmaxf(v.z, v.w));
}

// One thread = 4 contiguous float4 streaming loads (16 elements).
// Exact coverage: gridDim.x*blockDim.x == n/16.
__global__ void sdp_minmax_kernel(const float4* __restrict__ x) {
    const size_t base = ((size_t)blockIdx.x * blockDim.x + threadIdx.x) * 4;
    float4 v0 = __ldcs(&x[base + 0]);
    float4 v1 = __ldcs(&x[base + 1]);
    float4 v2 = __ldcs(&x[base + 2]);
    float4 v3 = __ldcs(&x[base + 3]);

    float lmin = fminf(fminf(v4min(v0), v4min(v1)), fminf(v4min(v2), v4min(v3)));
    float lmax = fmaxf(fmaxf(v4max(v0), v4max(v1)), fmaxf(v4max(v2), v4max(v3)));
    lmin = fminf(lmin, 0.0f);
    lmax = fmaxf(lmax, 0.0f);

    unsigned int emin = __reduce_min_sync(0xFFFFFFFFu, enc_f(lmin));
    unsigned int emax = __reduce_max_sync(0xFFFFFFFFu, enc_f(lmax));

    __shared__ unsigned int smin[8], smax[8];
    const int lane = threadIdx.x & 31;
    const int warp = threadIdx.x >> 5;
    if (lane == 0) { smin[warp] = emin; smax[warp] = emax; }
    __syncthreads();
    if (threadIdx.x < 8) {
        emin = __reduce_min_sync(0xFFu, smin[threadIdx.x]);
        emax = __reduce_max_sync(0xFFu, smax[threadIdx.x]);
        if (threadIdx.x == 0) {
            atomicMin(&g_min_enc, emin);
            atomicMax(&g_max_enc, emax);
        }
    }
    // Let the dependent quant grid start launching into freed slots.
    cudaTriggerProgrammaticLaunchCompletion();
}

// compare-exchange: u becomes max, v becomes min
#define SDP_CE(u, v) { float _hi = fmaxf(u, v), _lo = fminf(u, v); u = _hi; v = _lo; }

__device__ __forceinline__ void sdp_process_group(
    float4 va, float4 vb, float scale, float inv_scale,
    float4& oa, float4& ob)
{
    float xv[8]  = {va.x, va.y, va.z, va.w, vb.x, vb.y, vb.z, vb.w};
    float q[8];
    float mag[8];

    #pragma unroll
    for (int i = 0; i < 8; i++) {
        // Reciprocal-multiply fast path; can only flip round-half-to-even on
        // a near-.5 tie: detect and redo with exact IEEE division (rare).
        float y = xv[i] * inv_scale;
        float r = rintf(y);
        if (fabsf(fabsf(y - r) - 0.5f) < 1e-3f) {
            r = rintf(__fdiv_rn(xv[i], scale));
        }
        r = fminf(fmaxf(r, -128.0f), 127.0f);
        q[i]   = r;
        mag[i] = fabsf(r);   // integer-valued, 0..128
    }

    // 4th-largest of 8 via two sorted-4 runs + merge rank selection.
    float a0 = mag[0], a1 = mag[1], a2 = mag[2], a3 = mag[3];
    float b0 = mag[4], b1 = mag[5], b2 = mag[6], b3 = mag[7];
    SDP_CE(a0, a1); SDP_CE(a2, a3); SDP_CE(a0, a2); SDP_CE(a1, a3); SDP_CE(a1, a2);
    SDP_CE(b0, b1); SDP_CE(b2, b3); SDP_CE(b0, b2); SDP_CE(b1, b3); SDP_CE(b1, b2);
    float thr = fmaxf(fmaxf(a3, b3),
                      fmaxf(fminf(a0, b2), fmaxf(fminf(a1, b1), fminf(a2, b0))));

    #pragma unroll
    for (int i = 0; i < 8; i++) {
        const float tr16 = floorf(mag[i] * 0.0625f) * 16.0f;
        const float val  = (mag[i] >= thr) ? mag[i] : tr16;
        const float x_sdp = scale * copysignf(val, q[i]);
        xv[i] = xv[i] + (x_sdp - xv[i]);   // replicate reference rounding
    }

    oa = make_float4(xv[0], xv[1], xv[2], xv[3]);
    ob = make_float4(xv[4], xv[5], xv[6], xv[7]);
}

// One thread = two groups (16 elements, 4 LDG.128). Scale-independent loads
// issue BEFORE the grid dependency sync (PDL prologue overlap).
__global__ void sdp_quant_kernel(const float4* __restrict__ x,
                                 float4* __restrict__ out) {
    const size_t base = ((size_t)blockIdx.x * blockDim.x + threadIdx.x) * 4;
    float4 v0 = __ldcs(&x[base + 0]);
    float4 v1 = __ldcs(&x[base + 1]);
    float4 v2 = __ldcs(&x[base + 2]);
    float4 v3 = __ldcs(&x[base + 3]);

    // Wait for the minmax grid to fully complete (makes its atomics visible).
    cudaGridDependencySynchronize();

    const float r_min = dec_f(*(volatile unsigned int*)&g_min_enc);
    const float r_max = dec_f(*(volatile unsigned int*)&g_max_enc);
    const float scale = fmaxf(__fdiv_rn(r_max - r_min, 255.0f), 1e-8f);
    const float inv_scale = __frcp_rn(scale);

    float4 o0, o1, o2, o3;
    sdp_process_group(v0, v1, scale, inv_scale, o0, o1);
    sdp_process_group(v2, v3, scale, inv_scale, o2, o3);

    __stcs(&out[base + 0], o0);
    __stcs(&out[base + 1], o1);
    __stcs(&out[base + 2], o2);
    __stcs(&out[base + 3], o3);
}

extern "C" void kernel_launch(void* const* d_in, const int* in_sizes, int n_in,
                              void* d_out, int out_size) {
    const float* x = (const float*)d_in[0];
    float* out = (float*)d_out;
    const int n = in_sizes[0];          // 67,108,864

    const int threads = 256;
    const int blocks = n / (threads * 16);   // 16 elements per thread

    sdp_minmax_kernel<<<blocks, threads>>>((const float4*)x);

    // Quant with programmatic dependent launch: prologue (loads) may overlap
    // the minmax drain; cudaGridDependencySynchronize() enforces ordering.
    cudaLaunchConfig_t cfg = {};
    cfg.gridDim = dim3(blocks);
    cfg.blockDim = dim3(threads);
    cfg.dynamicSmemBytes = 0;
    cfg.stream = 0;   // same (legacy default) stream as the <<<>>> launch
    cudaLaunchAttribute attr[1];
    attr[0].id = cudaLaunchAttributeProgrammaticStreamSerialization;
    attr[0].val.programmaticStreamSerializationAllowed = 1;
    cfg.attrs = attr;
    cfg.numAttrs = 1;
    cudaLaunchKernelEx(&cfg, sdp_quant_kernel, (const float4*)x, (float4*)out);
}

// round 11
// speedup vs baseline: 1.1241x; 1.0289x over previous
#include <cuda_runtime.h>
#include <cstdint>

// ---------------------------------------------------------------------------
// SDPQuantizer: global min/max -> int8 quantize -> split high/low nibble ->
// per-8-group top-4 mask on low nibble -> dequantize.
// x: (8, 4096, 2048) fp32, 67,108,864 elements (256 MB). Output fp32.
//
// R3-proven two-kernel structure (minmax 49.3us, quant 85.9us) + sync-FIRST
// PDL: quant blocks pre-launch into SM slots freed by the draining minmax
// grid but issue NO memory work until cudaGridDependencySynchronize()
// releases (R10 showed prologue-load overlap contends and regresses; this
// variant captures only the drain/launch-ramp overlap).
// ---------------------------------------------------------------------------

__device__ unsigned int g_min_enc = 0x80000000u;  // enc(0.0f)
__device__ unsigned int g_max_enc = 0x80000000u;

__device__ __forceinline__ unsigned int enc_f(float f) {
    unsigned int u = __float_as_uint(f);
    return (u & 0x80000000u) ? ~u : (u | 0x80000000u);
}
__device__ __forceinline__ float dec_f(unsigned int u) {
    return (u & 0x80000000u) ? __uint_as_float(u & 0x7FFFFFFFu)
                             : __uint_as_float(~u);
}
__device__ __forceinline__ float v4min(float4 v) {
    return fminf(fminf(v.x, v.y), fminf(v.z, v.w));
}
__device__ __forceinline__ float v4max(float4 v) {
    return fmaxf(fmaxf(v.x, v.y), fmaxf(v.z, v.w));
}

// One thread = 4 contiguous float4 streaming loads (16 elements).
// Exact coverage: gridDim.x*blockDim.x == n/16.
__global__ void sdp_minmax_kernel(const float4* __restrict__ x) {
    const size_t base = ((size_t)blockIdx.x * blockDim.x + threadIdx.x) * 4;
    float4 v0 = __ldcs(&x[base + 0]);
    float4 v1 = __ldcs(&x[base + 1]);
    float4 v2 = __ldcs(&x[base + 2]);
    float4 v3 = __ldcs(&x[base + 3]);

    float lmin = fminf(fminf(v4min(v0), v4min(v1)), fminf(v4min(v2), v4min(v3)));
    float lmax = fmaxf(fmaxf(v4max(v0), v4max(v1)), fmaxf(v4max(v2), v4max(v3)));
    lmin = fminf(lmin, 0.0f);
    lmax = fmaxf(lmax, 0.0f);

    unsigned int emin = __reduce_min_sync(0xFFFFFFFFu, enc_f(lmin));
    unsigned int emax = __reduce_max_sync(0xFFFFFFFFu, enc_f(lmax));

    __shared__ unsigned int smin[8], smax[8];
    const int lane = threadIdx.x & 31;
    const int warp = threadIdx.x >> 5;
    if (lane == 0) { smin[warp] = emin; smax[warp] = emax; }
    __syncthreads();
    if (threadIdx.x < 8) {
        emin = __reduce_min_sync(0xFFu, smin[threadIdx.x]);
        emax = __reduce_max_sync(0xFFu, smax[threadIdx.x]);
        if (threadIdx.x == 0) {
            atomicMin(&g_min_enc, emin);
            atomicMax(&g_max_enc, emax);
        }
    }
    // Allow dependent-grid blocks to pre-launch into freed slots.
    cudaTriggerProgrammaticLaunchCompletion();
}

// compare-exchange: u becomes max, v becomes min
#define SDP_CE(u, v) { float _hi = fmaxf(u, v), _lo = fminf(u, v); u = _hi; v = _lo; }

__device__ __forceinline__ void sdp_process_group(
    float4 va, float4 vb, float scale, float inv_scale,
    float4& oa, float4& ob)
{
    float xv[8]  = {va.x, va.y, va.z, va.w, vb.x, vb.y, vb.z, vb.w};
    float q[8];
    float mag[8];

    #pragma unroll
    for (int i = 0; i < 8; i++) {
        // Reciprocal-multiply fast path; can only flip round-half-to-even on
        // a near-.5 tie: detect and redo with exact IEEE division (rare).
        float y = xv[i] * inv_scale;
        float r = rintf(y);
        if (fabsf(fabsf(y - r) - 0.5f) < 1e-3f) {
            r = rintf(__fdiv_rn(xv[i], scale));
        }
        r = fminf(fmaxf(r, -128.0f), 127.0f);
        q[i]   = r;
        mag[i] = fabsf(r);   // integer-valued, 0..128
    }

    // 4th-largest of 8 via two sorted-4 runs + merge rank selection.
    float a0 = mag[0], a1 = mag[1], a2 = mag[2], a3 = mag[3];
    float b0 = mag[4], b1 = mag[5], b2 = mag[6], b3 = mag[7];
    SDP_CE(a0, a1); SDP_CE(a2, a3); SDP_CE(a0, a2); SDP_CE(a1, a3); SDP_CE(a1, a2);
    SDP_CE(b0, b1); SDP_CE(b2, b3); SDP_CE(b0, b2); SDP_CE(b1, b3); SDP_CE(b1, b2);
    float thr = fmaxf(fmaxf(a3, b3),
                      fmaxf(fminf(a0, b2), fmaxf(fminf(a1, b1), fminf(a2, b0))));

    #pragma unroll
    for (int i = 0; i < 8; i++) {
        const float tr16 = floorf(mag[i] * 0.0625f) * 16.0f;
        const float val  = (mag[i] >= thr) ? mag[i] : tr16;
        const float x_sdp = scale * copysignf(val, q[i]);
        xv[i] = xv[i] + (x_sdp - xv[i]);   // replicate reference rounding
    }

    oa = make_float4(xv[0], xv[1], xv[2], xv[3]);
    ob = make_float4(xv[4], xv[5], xv[6], xv[7]);
}

// One thread = two groups (16 elements, 4 LDG.128). Dependency sync comes
// FIRST: no memory work until the minmax grid fully completes.
__global__ void sdp_quant_kernel(const float4* __restrict__ x,
                                 float4* __restrict__ out) {
    cudaGridDependencySynchronize();

    const float r_min = dec_f(*(volatile unsigned int*)&g_min_enc);
    const float r_max = dec_f(*(volatile unsigned int*)&g_max_enc);
    const float scale = fmaxf(__fdiv_rn(r_max - r_min, 255.0f), 1e-8f);
    const float inv_scale = __frcp_rn(scale);

    const size_t base = ((size_t)blockIdx.x * blockDim.x + threadIdx.x) * 4;
    float4 v0 = __ldcs(&x[base + 0]);
    float4 v1 = __ldcs(&x[base + 1]);
    float4 v2 = __ldcs(&x[base + 2]);
    float4 v3 = __ldcs(&x[base + 3]);

    float4 o0, o1, o2, o3;
    sdp_process_group(v0, v1, scale, inv_scale, o0, o1);
    sdp_process_group(v2, v3, scale, inv_scale, o2, o3);

    __stcs(&out[base + 0], o0);
    __stcs(&out[base + 1], o1);
    __stcs(&out[base + 2], o2);
    __stcs(&out[base + 3], o3);
}

extern "C" void kernel_launch(void* const* d_in, const int* in_sizes, int n_in,
                              void* d_out, int out_size) {
    const float* x = (const float*)d_in[0];
    float* out = (float*)d_out;
    const int n = in_sizes[0];          // 67,108,864

    const int threads = 256;
    const int blocks = n / (threads * 16);   // 16 elements per thread

    sdp_minmax_kernel<<<blocks, threads>>>((const float4*)x);

    cudaLaunchConfig_t cfg = {};
    cfg.gridDim = dim3(blocks);
    cfg.blockDim = dim3(threads);
    cfg.dynamicSmemBytes = 0;
    cfg.stream = 0;
    cudaLaunchAttribute attr[1];
    attr[0].id = cudaLaunchAttributeProgrammaticStreamSerialization;
    attr[0].val.programmaticStreamSerializationAllowed = 1;
    cfg.attrs = attr;
    cfg.numAttrs = 1;
    cudaLaunchKernelEx(&cfg, sdp_quant_kernel, (const float4*)x, (float4*)out);
}

// round 12
// speedup vs baseline: 1.2141x; 1.0800x over previous
#include <cuda_runtime.h>
#include <cstdint>

// ---------------------------------------------------------------------------
// SDPQuantizer: global min/max -> int8 quantize -> split high/low nibble ->
// per-8-group top-4 mask on low nibble -> dequantize.
// x: (8, 4096, 2048) fp32 = 67,108,864 elements = 256 MB. Output fp32.
//
// Kernel 1 (minmax): TMA bulk-copy read engine. Each of 8192 CTAs copies its
//   32KB span into SMEM via cp.async.bulk + mbarrier, reduces from SMEM
//   (conflict-free LDS.128), REDUX + one atomic per block. Tests whether the
//   measured 5.2 TB/s pure-LDG read wall is an LDG-path artifact.
// Kernel 2 (quant): R3-proven verbatim (85.9us, 5.96 TB/s).
// ---------------------------------------------------------------------------

__device__ unsigned int g_min_enc = 0x80000000u;  // enc(0.0f)
__device__ unsigned int g_max_enc = 0x80000000u;

__device__ __forceinline__ unsigned int enc_f(float f) {
    unsigned int u = __float_as_uint(f);
    return (u & 0x80000000u) ? ~u : (u | 0x80000000u);
}
__device__ __forceinline__ float dec_f(unsigned int u) {
    return (u & 0x80000000u) ? __uint_as_float(u & 0x7FFFFFFFu)
                             : __uint_as_float(~u);
}
__device__ __forceinline__ float v4min(float4 v) {
    return fminf(fminf(v.x, v.y), fminf(v.z, v.w));
}
__device__ __forceinline__ float v4max(float4 v) {
    return fmaxf(fmaxf(v.x, v.y), fmaxf(v.z, v.w));
}
__device__ __forceinline__ unsigned int smem_u32(const void* p) {
    unsigned int a;
    asm("{ .reg .u64 t; cvta.to.shared.u64 t, %1; cvt.u32.u64 %0, t; }"
        : "=r"(a) : "l"(p));
    return a;
}

#define SDP_CHUNK_BYTES 32768           // 32KB per CTA = 2048 float4
#define SDP_CHUNK_V4    2048

// One CTA = one 32KB chunk via cp.async.bulk into SMEM, then reduce.
__global__ void __launch_bounds__(256)
sdp_minmax_kernel(const float* __restrict__ x) {
    __shared__ alignas(128) float4 buf[SDP_CHUNK_V4];
    __shared__ alignas(8) unsigned long long mbar;

    const int t = threadIdx.x;
    const unsigned int mbar_a = smem_u32(&mbar);
    const unsigned int buf_a  = smem_u32(buf);

    if (t == 0) {
        asm volatile("mbarrier.init.shared.b64 [%0], 1;" :: "r"(mbar_a) : "memory");
        asm volatile("fence.proxy.async.shared::cta;" ::: "memory");
    }
    __syncthreads();

    if (t == 0) {
        asm volatile("mbarrier.arrive.expect_tx.shared.b64 _, [%0], %1;"
                     :: "r"(mbar_a), "r"((unsigned)SDP_CHUNK_BYTES) : "memory");
        const char* src = (const char*)x + (size_t)blockIdx.x * SDP_CHUNK_BYTES;
        asm volatile(
            "cp.async.bulk.shared::cta.global.mbarrier::complete_tx::bytes "
            "[%0], [%1], %2, [%3];"
            :: "r"(buf_a), "l"(src), "r"((unsigned)SDP_CHUNK_BYTES), "r"(mbar_a)
            : "memory");
    }

    // All threads wait for the bulk copy (parity 0: barrier is freshly
    // initialized each launch, so replay-safe).
    asm volatile(
        "{\n\t"
        ".reg .pred P;\n\t"
        "WAIT_%=:\n\t"
        "mbarrier.try_wait.parity.acquire.cta.shared::cta.b64 P, [%0], 0, 0x989680;\n\t"
        "@P bra DONE_%=;\n\t"
        "bra WAIT_%=;\n\t"
        "DONE_%=:\n\t"
        "}"
        :: "r"(mbar_a) : "memory");

    // Reduce 8 float4 per thread, stride-1 across threads (conflict-free).
    float lmin = 0.0f, lmax = 0.0f;
    #pragma unroll
    for (int k = 0; k < 8; k++) {
        float4 v = buf[t + k * 256];
        lmin = fminf(lmin, v4min(v));
        lmax = fmaxf(lmax, v4max(v));
    }

    unsigned int emin = __reduce_min_sync(0xFFFFFFFFu, enc_f(lmin));
    unsigned int emax = __reduce_max_sync(0xFFFFFFFFu, enc_f(lmax));

    __shared__ unsigned int smin[8], smax[8];
    const int lane = t & 31;
    const int warp = t >> 5;
    if (lane == 0) { smin[warp] = emin; smax[warp] = emax; }
    __syncthreads();
    if (t < 8) {
        emin = __reduce_min_sync(0xFFu, smin[t]);
        emax = __reduce_max_sync(0xFFu, smax[t]);
        if (t == 0) {
            atomicMin(&g_min_enc, emin);
            atomicMax(&g_max_enc, emax);
        }
    }
}

// compare-exchange: u becomes max, v becomes min
#define SDP_CE(u, v) { float _hi = fmaxf(u, v), _lo = fminf(u, v); u = _hi; v = _lo; }

__device__ __forceinline__ void sdp_process_group(
    float4 va, float4 vb, float scale, float inv_scale,
    float4& oa, float4& ob)
{
    float xv[8]  = {va.x, va.y, va.z, va.w, vb.x, vb.y, vb.z, vb.w};
    float q[8];
    float mag[8];

    #pragma unroll
    for (int i = 0; i < 8; i++) {
        // Reciprocal-multiply fast path; can only flip round-half-to-even on
        // a near-.5 tie: detect and redo with exact IEEE division (rare).
        float y = xv[i] * inv_scale;
        float r = rintf(y);
        if (fabsf(fabsf(y - r) - 0.5f) < 1e-3f) {
            r = rintf(__fdiv_rn(xv[i], scale));
        }
        r = fminf(fmaxf(r, -128.0f), 127.0f);
        q[i]   = r;
        mag[i] = fabsf(r);   // integer-valued, 0..128
    }

    // 4th-largest of 8 via two sorted-4 runs + merge rank selection.
    float a0 = mag[0], a1 = mag[1], a2 = mag[2], a3 = mag[3];
    float b0 = mag[4], b1 = mag[5], b2 = mag[6], b3 = mag[7];
    SDP_CE(a0, a1); SDP_CE(a2, a3); SDP_CE(a0, a2); SDP_CE(a1, a3); SDP_CE(a1, a2);
    SDP_CE(b0, b1); SDP_CE(b2, b3); SDP_CE(b0, b2); SDP_CE(b1, b3); SDP_CE(b1, b2);
    float thr = fmaxf(fmaxf(a3, b3),
                      fmaxf(fminf(a0, b2), fmaxf(fminf(a1, b1), fminf(a2, b0))));

    #pragma unroll
    for (int i = 0; i < 8; i++) {
        const float tr16 = floorf(mag[i] * 0.0625f) * 16.0f;
        const float val  = (mag[i] >= thr) ? mag[i] : tr16;
        const float x_sdp = scale * copysignf(val, q[i]);
        xv[i] = xv[i] + (x_sdp - xv[i]);   // replicate reference rounding
    }

    oa = make_float4(xv[0], xv[1], xv[2], xv[3]);
    ob = make_float4(xv[4], xv[5], xv[6], xv[7]);
}

// One thread = two groups (16 elements, 4 LDG.128). Forward order, exact
// coverage grid. (R3-proven: 85.9us, 5.96 TB/s.)
__global__ void sdp_quant_kernel(const float4* __restrict__ x,
                                 float4* __restrict__ out) {
    const float r_min = dec_f(g_min_enc);
    const float r_max = dec_f(g_max_enc);
    const float scale = fmaxf(__fdiv_rn(r_max - r_min, 255.0f), 1e-8f);
    const float inv_scale = __frcp_rn(scale);

    const size_t base = ((size_t)blockIdx.x * blockDim.x + threadIdx.x) * 4;
    float4 v0 = __ldcs(&x[base + 0]);
    float4 v1 = __ldcs(&x[base + 1]);
    float4 v2 = __ldcs(&x[base + 2]);
    float4 v3 = __ldcs(&x[base + 3]);

    float4 o0, o1, o2, o3;
    sdp_process_group(v0, v1, scale, inv_scale, o0, o1);
    sdp_process_group(v2, v3, scale, inv_scale, o2, o3);

    __stcs(&out[base + 0], o0);
    __stcs(&out[base + 1], o1);
    __stcs(&out[base + 2], o2);
    __stcs(&out[base + 3], o3);
}

extern "C" void kernel_launch(void* const* d_in, const int* in_sizes, int n_in,
                              void* d_out, int out_size) {
    const float* x = (const float*)d_in[0];
    float* out = (float*)d_out;
    const int n = in_sizes[0];          // 67,108,864 floats = 256 MB

    const int threads = 256;

    const int mm_blocks = (int)((size_t)n * 4 / SDP_CHUNK_BYTES);  // 8192
    sdp_minmax_kernel<<<mm_blocks, threads>>>(x);

    const int q_blocks = n / (threads * 16);    // 16 elements per thread
    sdp_quant_kernel<<<q_blocks, threads>>>((const float4*)x, (float4*)out);
}

// round 13
// speedup vs baseline: 1.3003x; 1.0710x over previous
#include <cuda_runtime.h>
#include <cstdint>

// ---------------------------------------------------------------------------
// SDPQuantizer: global min/max -> int8 quantize -> split high/low nibble ->
// per-8-group top-4 mask on low nibble -> dequantize.
// x: (8, 4096, 2048) fp32 = 67,108,864 elements = 256 MB. Output fp32.
//
// Kernel 1 (minmax, R12-proven): TMA bulk-copy read engine. Each of 8192
//   CTAs copies its 32KB span into SMEM via cp.async.bulk + mbarrier,
//   reduces from SMEM, REDUX + one atomic per block.  (46.7us measured)
// Kernel 2 (quant): pair-layout addressing. Thread t owns float4 pairs
//   (2t, 2t+1) and (512+2t, 512+2t+1) of a 1024-float4 chunk: 32B lane
//   stride halves L1tex wavefronts per LDG/STG vs the previous 64B stride
//   (ncu showed L1=75.9% > DRAM=70.5%: L1 wavefront-bound).
// ---------------------------------------------------------------------------

__device__ unsigned int g_min_enc = 0x80000000u;  // enc(0.0f)
__device__ unsigned int g_max_enc = 0x80000000u;

__device__ __forceinline__ unsigned int enc_f(float f) {
    unsigned int u = __float_as_uint(f);
    return (u & 0x80000000u) ? ~u : (u | 0x80000000u);
}
__device__ __forceinline__ float dec_f(unsigned int u) {
    return (u & 0x80000000u) ? __uint_as_float(u & 0x7FFFFFFFu)
                             : __uint_as_float(~u);
}
__device__ __forceinline__ float v4min(float4 v) {
    return fminf(fminf(v.x, v.y), fminf(v.z, v.w));
}
__device__ __forceinline__ float v4max(float4 v) {
    return fmaxf(fmaxf(v.x, v.y), fmaxf(v.z, v.w));
}
__device__ __forceinline__ unsigned int smem_u32(const void* p) {
    unsigned int a;
    asm("{ .reg .u64 t; cvta.to.shared.u64 t, %1; cvt.u32.u64 %0, t; }"
        : "=r"(a) : "l"(p));
    return a;
}

#define SDP_CHUNK_BYTES 32768           // 32KB per CTA = 2048 float4
#define SDP_CHUNK_V4    2048

// One CTA = one 32KB chunk via cp.async.bulk into SMEM, then reduce.
__global__ void __launch_bounds__(256)
sdp_minmax_kernel(const float* __restrict__ x) {
    __shared__ alignas(128) float4 buf[SDP_CHUNK_V4];
    __shared__ alignas(8) unsigned long long mbar;

    const int t = threadIdx.x;
    const unsigned int mbar_a = smem_u32(&mbar);
    const unsigned int buf_a  = smem_u32(buf);

    if (t == 0) {
        asm volatile("mbarrier.init.shared.b64 [%0], 1;" :: "r"(mbar_a) : "memory");
        asm volatile("fence.proxy.async.shared::cta;" ::: "memory");
    }
    __syncthreads();

    if (t == 0) {
        asm volatile("mbarrier.arrive.expect_tx.shared.b64 _, [%0], %1;"
                     :: "r"(mbar_a), "r"((unsigned)SDP_CHUNK_BYTES) : "memory");
        const char* src = (const char*)x + (size_t)blockIdx.x * SDP_CHUNK_BYTES;
        asm volatile(
            "cp.async.bulk.shared::cta.global.mbarrier::complete_tx::bytes "
            "[%0], [%1], %2, [%3];"
            :: "r"(buf_a), "l"(src), "r"((unsigned)SDP_CHUNK_BYTES), "r"(mbar_a)
            : "memory");
    }

    // All threads wait for the bulk copy (parity 0; barrier freshly
    // initialized each launch -> replay-safe).
    asm volatile(
        "{\n\t"
        ".reg .pred P;\n\t"
        "WAIT_%=:\n\t"
        "mbarrier.try_wait.parity.acquire.cta.shared::cta.b64 P, [%0], 0, 0x989680;\n\t"
        "@P bra DONE_%=;\n\t"
        "bra WAIT_%=;\n\t"
        "DONE_%=:\n\t"
        "}"
        :: "r"(mbar_a) : "memory");

    // Reduce 8 float4 per thread, stride-1 across threads (conflict-free).
    float lmin = 0.0f, lmax = 0.0f;
    #pragma unroll
    for (int k = 0; k < 8; k++) {
        float4 v = buf[t + k * 256];
        lmin = fminf(lmin, v4min(v));
        lmax = fmaxf(lmax, v4max(v));
    }

    unsigned int emin = __reduce_min_sync(0xFFFFFFFFu, enc_f(lmin));
    unsigned int emax = __reduce_max_sync(0xFFFFFFFFu, enc_f(lmax));

    __shared__ unsigned int smin[8], smax[8];
    const int lane = t & 31;
    const int warp = t >> 5;
    if (lane == 0) { smin[warp] = emin; smax[warp] = emax; }
    __syncthreads();
    if (t < 8) {
        emin = __reduce_min_sync(0xFFu, smin[t]);
        emax = __reduce_max_sync(0xFFu, smax[t]);
        if (t == 0) {
            atomicMin(&g_min_enc, emin);
            atomicMax(&g_max_enc, emax);
        }
    }
}

// compare-exchange: u becomes max, v becomes min
#define SDP_CE(u, v) { float _hi = fmaxf(u, v), _lo = fminf(u, v); u = _hi; v = _lo; }

__device__ __forceinline__ void sdp_process_group(
    float4 va, float4 vb, float scale, float inv_scale,
    float4& oa, float4& ob)
{
    float xv[8]  = {va.x, va.y, va.z, va.w, vb.x, vb.y, vb.z, vb.w};
    float q[8];
    float mag[8];

    #pragma unroll
    for (int i = 0; i < 8; i++) {
        // Reciprocal-multiply fast path; can only flip round-half-to-even on
        // a near-.5 tie: detect and redo with exact IEEE division (rare).
        float y = xv[i] * inv_scale;
        float r = rintf(y);
        if (fabsf(fabsf(y - r) - 0.5f) < 1e-3f) {
            r = rintf(__fdiv_rn(xv[i], scale));
        }
        r = fminf(fmaxf(r, -128.0f), 127.0f);
        q[i]   = r;
        mag[i] = fabsf(r);   // integer-valued, 0..128
    }

    // 4th-largest of 8 via two sorted-4 runs + merge rank selection.
    float a0 = mag[0], a1 = mag[1], a2 = mag[2], a3 = mag[3];
    float b0 = mag[4], b1 = mag[5], b2 = mag[6], b3 = mag[7];
    SDP_CE(a0, a1); SDP_CE(a2, a3); SDP_CE(a0, a2); SDP_CE(a1, a3); SDP_CE(a1, a2);
    SDP_CE(b0, b1); SDP_CE(b2, b3); SDP_CE(b0, b2); SDP_CE(b1, b3); SDP_CE(b1, b2);
    float thr = fmaxf(fmaxf(a3, b3),
                      fmaxf(fminf(a0, b2), fmaxf(fminf(a1, b1), fminf(a2, b0))));

    #pragma unroll
    for (int i = 0; i < 8; i++) {
        const float tr16 = floorf(mag[i] * 0.0625f) * 16.0f;
        const float val  = (mag[i] >= thr) ? mag[i] : tr16;
        const float x_sdp = scale * copysignf(val, q[i]);
        xv[i] = xv[i] + (x_sdp - xv[i]);   // replicate reference rounding
    }

    oa = make_float4(xv[0], xv[1], xv[2], xv[3]);
    ob = make_float4(xv[4], xv[5], xv[6], xv[7]);
}

// One thread = two groups. Pair layout: thread t owns float4 pairs
// (2t, 2t+1) and (512+2t, 512+2t+1) of a 1024-float4 chunk -> 32B lane
// stride -> 8 lines per warp-LDG.128 instead of 16 (halved L1 wavefronts).
__global__ void sdp_quant_kernel(const float4* __restrict__ x,
                                 float4* __restrict__ out) {
    const float r_min = dec_f(g_min_enc);
    const float r_max = dec_f(g_max_enc);
    const float scale = fmaxf(__fdiv_rn(r_max - r_min, 255.0f), 1e-8f);
    const float inv_scale = __frcp_rn(scale);

    const size_t chunk = (size_t)blockIdx.x * 1024;   // float4 units
    const int t = threadIdx.x;
    const size_t i0 = chunk + 2 * t;          // first group (pair)
    const size_t i1 = chunk + 512 + 2 * t;    // second group (pair)

    float4 v0 = __ldcs(&x[i0]);
    float4 v1 = __ldcs(&x[i0 + 1]);
    float4 v2 = __ldcs(&x[i1]);
    float4 v3 = __ldcs(&x[i1 + 1]);

    float4 o0, o1, o2, o3;
    sdp_process_group(v0, v1, scale, inv_scale, o0, o1);
    sdp_process_group(v2, v3, scale, inv_scale, o2, o3);

    __stcs(&out[i0],     o0);
    __stcs(&out[i0 + 1], o1);
    __stcs(&out[i1],     o2);
    __stcs(&out[i1 + 1], o3);
}

extern "C" void kernel_launch(void* const* d_in, const int* in_sizes, int n_in,
                              void* d_out, int out_size) {
    const float* x = (const float*)d_in[0];
    float* out = (float*)d_out;
    const int n = in_sizes[0];          // 67,108,864 floats = 256 MB
    const int n4 = n >> 2;              // 16,777,216 float4

    const int threads = 256;

    const int mm_blocks = (int)((size_t)n * 4 / SDP_CHUNK_BYTES);  // 8192
    sdp_minmax_kernel<<<mm_blocks, threads>>>(x);

    const int q_blocks = n4 / 1024;     // 16384 chunks of 1024 float4
    sdp_quant_kernel<<<q_blocks, threads>>>((const float4*)x, (float4*)out);
}